// round 12
// baseline (speedup 1.0000x reference)
#include <cuda_runtime.h>
#include <stdint.h>

// Haar DWT level-1 on x: (B=32, L=4096, F=512) fp32.
// out[b, p, f]      = (x[b,2p,f] + x[b,2p+1,f]) / sqrt2   (p in [0,2048))
// out[b, 2048+p, f] = (x[b,2p,f] - x[b,2p+1,f]) / sqrt2
//
// R12 probe: native 256-bit global accesses (PTX ld/st.global.v8.f32,
// sm_100+). lane = f8 stride-1 (32B units) -> each warp ld/st covers 1024
// contiguous bytes in ONE instruction. One pair per thread, MLP=2x32B.

#define B 32
#define L 4096
#define F 512
#define HALF_L (L / 2)
#define F8 (F / 8)                        // 64 x 8-float chunks per row
#define TOTAL_T (B * HALF_L * F8)         // 4,194,304 threads

__device__ __forceinline__ void ldg_v8(const float* p, float* v) {
    asm volatile("ld.global.v8.f32 {%0,%1,%2,%3,%4,%5,%6,%7}, [%8];"
                 : "=f"(v[0]), "=f"(v[1]), "=f"(v[2]), "=f"(v[3]),
                   "=f"(v[4]), "=f"(v[5]), "=f"(v[6]), "=f"(v[7])
                 : "l"(p));
}

__device__ __forceinline__ void stg_v8(float* p, const float* v) {
    asm volatile("st.global.v8.f32 [%0], {%1,%2,%3,%4,%5,%6,%7,%8};"
                 :: "l"(p),
                    "f"(v[0]), "f"(v[1]), "f"(v[2]), "f"(v[3]),
                    "f"(v[4]), "f"(v[5]), "f"(v[6]), "f"(v[7])
                 : "memory");
}

__global__ __launch_bounds__(256) void haar_dwt_kernel(
    const float* __restrict__ x, float* __restrict__ out)
{
    int t = blockIdx.x * blockDim.x + threadIdx.x;

    int f8 = t & (F8 - 1);                // 0..63 (lane-contiguous, 32B units)
    int p  = (t >> 6) & (HALF_L - 1);     // 0..2047
    int b  = t >> 17;                     // 0..31

    long base_b = (long)b * (L * F);
    long in = base_b + (long)(2 * p) * F + f8 * 8;

    float x0[8], x1[8];
    ldg_v8(x + in,     x0);
    ldg_v8(x + in + F, x1);

    const float s = 0.70710678118654752440f;
    float ca[8], cd[8];
#pragma unroll
    for (int i = 0; i < 8; i++) {
        ca[i] = (x0[i] + x1[i]) * s;
        cd[i] = (x0[i] - x1[i]) * s;
    }

    long outA = base_b + (long)p * F + f8 * 8;
    long dOff = (long)HALF_L * F;

    stg_v8(out + outA,        ca);
    stg_v8(out + outA + dOff, cd);
}

extern "C" void kernel_launch(void* const* d_in, const int* in_sizes, int n_in,
                              void* d_out, int out_size)
{
    const float* x = (const float*)d_in[0];
    float* out = (float*)d_out;

    int threads = 256;
    int blocks = TOTAL_T / threads;       // 16384
    haar_dwt_kernel<<<blocks, threads>>>(x, out);
}

// round 13
// speedup vs baseline: 1.0012x; 1.0012x over previous
#include <cuda_runtime.h>
#include <stdint.h>

// Haar DWT level-1 on x: (B=32, L=4096, F=512) fp32.
// out[b, p, f]      = (x[b,2p,f] + x[b,2p+1,f]) / sqrt2   (p in [0,2048))
// out[b, 2048+p, f] = (x[b,2p,f] - x[b,2p+1,f]) / sqrt2
//
// FINAL — best of 12 measured variants (74.37us kernel, DRAM 81.7%,
// 6.48TB/s duty; useful app bandwidth ~7.2TB/s = 90% of 8TB/s spec).
//  - lane = f4, stride-1 float4 within warp: every LDG.128/STG.128 is a
//    512B lane-contiguous warp transaction (coalescing = the binding factor)
//  - MLP=4 per thread via two adjacent pairs (input rows 4p..4p+3):
//    1 contiguous read stream + 2 contiguous write streams per warp
//  - PLAIN loads/stores (all cache hints measured harmful or neutral)
//  - multi-wave launch (persistent grid-stride measured -5% DRAM duty)
// Remaining gap to spec = HBM3e R/W bus turnaround; confirmed not
// SM-controllable (MLP8 / v8-256bit / hints / persistence all neutral-or-worse).

#define B 32
#define L 4096
#define F 512
#define HALF_L (L / 2)
#define F4 (F / 4)                        // 128 float4 per row
#define PQ (HALF_L / 2)                   // 1024 quad-row groups
#define TOTAL_T (B * PQ * F4)             // 4,194,304 threads

__global__ __launch_bounds__(256) void haar_dwt_kernel(
    const float4* __restrict__ x, float4* __restrict__ out)
{
    int t = blockIdx.x * blockDim.x + threadIdx.x;

    int f4 = t & (F4 - 1);                // 0..127 (lane-contiguous)
    int p  = (t >> 7) & (PQ - 1);         // 0..1023 -> input rows 4p..4p+3
    int b  = t >> 17;                     // 0..31

    long row = (long)F4;
    long base_b = (long)b * (L * F4);

    long in = base_b + (long)(4 * p) * row + f4;

    // 4 independent coalesced loads from 4 consecutive rows
    float4 a0 = x[in];
    float4 a1 = x[in + row];
    float4 b0 = x[in + 2 * row];
    float4 b1 = x[in + 3 * row];

    const float s = 0.70710678118654752440f;
    float4 ca0, cd0, ca1, cd1;
    ca0.x = (a0.x + a1.x) * s;  cd0.x = (a0.x - a1.x) * s;
    ca0.y = (a0.y + a1.y) * s;  cd0.y = (a0.y - a1.y) * s;
    ca0.z = (a0.z + a1.z) * s;  cd0.z = (a0.z - a1.z) * s;
    ca0.w = (a0.w + a1.w) * s;  cd0.w = (a0.w - a1.w) * s;
    ca1.x = (b0.x + b1.x) * s;  cd1.x = (b0.x - b1.x) * s;
    ca1.y = (b0.y + b1.y) * s;  cd1.y = (b0.y - b1.y) * s;
    ca1.z = (b0.z + b1.z) * s;  cd1.z = (b0.z - b1.z) * s;
    ca1.w = (b0.w + b1.w) * s;  cd1.w = (b0.w - b1.w) * s;

    long outA = base_b + (long)(2 * p) * row + f4;
    long dOff = (long)HALF_L * row;

    out[outA]              = ca0;
    out[outA + row]        = ca1;
    out[outA + dOff]       = cd0;
    out[outA + dOff + row] = cd1;
}

extern "C" void kernel_launch(void* const* d_in, const int* in_sizes, int n_in,
                              void* d_out, int out_size)
{
    const float4* x = (const float4*)d_in[0];
    float4* out = (float4*)d_out;

    int threads = 256;
    int blocks = TOTAL_T / threads;       // 16384
    haar_dwt_kernel<<<blocks, threads>>>(x, out);
}